// round 1
// baseline (speedup 1.0000x reference)
#include <cuda_runtime.h>
#include <cstddef>

#define BB 4
#define CC 512
#define LL 2048
#define HH 8
#define DH 64

// Scratch: projected q/k/v in (B, C, L) layout, attention context in (B, L, C).
__device__ float g_qh[BB * CC * LL];
__device__ float g_kh[BB * CC * LL];
__device__ float g_vh[BB * CC * LL];
__device__ float g_ctx[BB * LL * CC];

// ---------------------------------------------------------------------------
// Projection GEMM, X in (B, C, L):  Y[b,o,l] = bias[o] + sum_c W[o,c] * X[b,c,l]
// Tile: 64 (o) x 64 (l), K-tile 16. 256 threads, 4x4 per thread.
// ---------------------------------------------------------------------------
__global__ __launch_bounds__(256) void proj_kernel(
    const float* __restrict__ W, const float* __restrict__ bias,
    const float* __restrict__ X, float* __restrict__ Y)
{
    __shared__ float Ws[16][68];  // [c][o]
    __shared__ float Xs[16][68];  // [c][l]

    const int l0 = blockIdx.x * 64;
    const int o0 = blockIdx.y * 64;
    const int b  = blockIdx.z;
    const float* Xb = X + (size_t)b * CC * LL;
    float*       Yb = Y + (size_t)b * CC * LL;

    const int tid = threadIdx.x;
    const int tx = tid & 15;        // -> l
    const int ty = tid >> 4;        // -> o

    float acc[4][4];
#pragma unroll
    for (int i = 0; i < 4; i++)
#pragma unroll
        for (int j = 0; j < 4; j++) acc[i][j] = 0.f;

    const int idx = tid * 4;
    const int wo = idx >> 4;        // 0..63
    const int wc = idx & 15;        // 0,4,8,12
    const int xc = idx >> 6;        // 0..15
    const int xl = idx & 63;        // 0..60

    for (int c0 = 0; c0 < CC; c0 += 16) {
        float4 w4 = *(const float4*)(W + (size_t)(o0 + wo) * CC + c0 + wc);
        Ws[wc + 0][wo] = w4.x; Ws[wc + 1][wo] = w4.y;
        Ws[wc + 2][wo] = w4.z; Ws[wc + 3][wo] = w4.w;
        float4 x4 = *(const float4*)(Xb + (size_t)(c0 + xc) * LL + l0 + xl);
        *(float4*)(&Xs[xc][xl]) = x4;
        __syncthreads();
#pragma unroll
        for (int kk = 0; kk < 16; kk++) {
            float4 a = *(const float4*)(&Ws[kk][ty * 4]);
            float4 x = *(const float4*)(&Xs[kk][tx * 4]);
            float av[4] = {a.x, a.y, a.z, a.w};
            float xv[4] = {x.x, x.y, x.z, x.w};
#pragma unroll
            for (int i = 0; i < 4; i++)
#pragma unroll
                for (int j = 0; j < 4; j++) acc[i][j] += av[i] * xv[j];
        }
        __syncthreads();
    }

#pragma unroll
    for (int i = 0; i < 4; i++) {
        float bbv = bias[o0 + ty * 4 + i];
        float4 r = make_float4(acc[i][0] + bbv, acc[i][1] + bbv,
                               acc[i][2] + bbv, acc[i][3] + bbv);
        *(float4*)(Yb + (size_t)(o0 + ty * 4 + i) * LL + l0 + tx * 4) = r;
    }
}

// ---------------------------------------------------------------------------
// Output projection GEMM, X in (B, L, C):  Y[b,o,l] = bias[o] + sum_c W[o,c] * XT[b,l,c]
// ---------------------------------------------------------------------------
__global__ __launch_bounds__(256) void projT_kernel(
    const float* __restrict__ W, const float* __restrict__ bias,
    const float* __restrict__ XT, float* __restrict__ Y)
{
    __shared__ float Ws[16][68];  // [c][o]
    __shared__ float Xs[16][68];  // [c][l]

    const int l0 = blockIdx.x * 64;
    const int o0 = blockIdx.y * 64;
    const int b  = blockIdx.z;
    const float* Xb = XT + (size_t)b * LL * CC;
    float*       Yb = Y + (size_t)b * CC * LL;

    const int tid = threadIdx.x;
    const int tx = tid & 15;
    const int ty = tid >> 4;

    float acc[4][4];
#pragma unroll
    for (int i = 0; i < 4; i++)
#pragma unroll
        for (int j = 0; j < 4; j++) acc[i][j] = 0.f;

    const int idx = tid * 4;
    const int wo = idx >> 4;
    const int wc = idx & 15;
    const int xl = idx >> 4;        // 0..63  (l)
    const int xc = idx & 15;        // 0,4,8,12 (c)

    for (int c0 = 0; c0 < CC; c0 += 16) {
        float4 w4 = *(const float4*)(W + (size_t)(o0 + wo) * CC + c0 + wc);
        Ws[wc + 0][wo] = w4.x; Ws[wc + 1][wo] = w4.y;
        Ws[wc + 2][wo] = w4.z; Ws[wc + 3][wo] = w4.w;
        float4 x4 = *(const float4*)(Xb + (size_t)(l0 + xl) * CC + c0 + xc);
        Xs[xc + 0][xl] = x4.x; Xs[xc + 1][xl] = x4.y;
        Xs[xc + 2][xl] = x4.z; Xs[xc + 3][xl] = x4.w;
        __syncthreads();
#pragma unroll
        for (int kk = 0; kk < 16; kk++) {
            float4 a = *(const float4*)(&Ws[kk][ty * 4]);
            float4 x = *(const float4*)(&Xs[kk][tx * 4]);
            float av[4] = {a.x, a.y, a.z, a.w};
            float xv[4] = {x.x, x.y, x.z, x.w};
#pragma unroll
            for (int i = 0; i < 4; i++)
#pragma unroll
                for (int j = 0; j < 4; j++) acc[i][j] += av[i] * xv[j];
        }
        __syncthreads();
    }

#pragma unroll
    for (int i = 0; i < 4; i++) {
        float bbv = bias[o0 + ty * 4 + i];
        float4 r = make_float4(acc[i][0] + bbv, acc[i][1] + bbv,
                               acc[i][2] + bbv, acc[i][3] + bbv);
        *(float4*)(Yb + (size_t)(o0 + ty * 4 + i) * LL + l0 + tx * 4) = r;
    }
}

// ---------------------------------------------------------------------------
// Flash attention: one CTA per (64-query block, head, batch).
// Q tile resident in smem; stream 64-key blocks with online softmax.
// Thread map (16x16): q = ty*4+i, k/d = tx*4+j. Row (k) reductions via
// 16-lane shfl butterflies (lanes 0-15 / 16-31 each own one q group).
// ---------------------------------------------------------------------------
#define ATTN_SMEM_FLOATS (64 * 64 + 64 * 64 + 64 * 68 + 64 * 68 + 64)
#define ATTN_SMEM_BYTES  (ATTN_SMEM_FLOATS * 4)

__global__ __launch_bounds__(256) void attn_kernel(const float* __restrict__ mask)
{
    extern __shared__ float sm[];
    float* Qs = sm;                   // [d][q]  64x64
    float* Ks = Qs + 64 * 64;         // [d][k]  64x64
    float* Vs = Ks + 64 * 64;         // [k][d]  64x68 (transposed V)
    float* Ps = Vs + 64 * 68;         // [q][k]  64x68
    float* Ms = Ps + 64 * 68;         // [k]     64

    const int l0 = blockIdx.x * 64;
    const int h  = blockIdx.y;
    const int b  = blockIdx.z;

    const int tid = threadIdx.x;
    const int tx = tid & 15;
    const int ty = tid >> 4;
    const int qoff = ty * 4;
    const int doff = tx * 4;   // also k-offset in S phase

    const float* qbase = g_qh + ((size_t)b * CC + h * DH) * LL;
    const float* kbase = g_kh + ((size_t)b * CC + h * DH) * LL;
    const float* vbase = g_vh + ((size_t)b * CC + h * DH) * LL;
    const float* maskb = mask + (size_t)b * LL;

    // Load Q tile (64 d x 64 q), coalesced over q.
#pragma unroll
    for (int r = 0; r < 4; r++) {
        int li = tid * 4 + r * 1024;
        int d = li >> 6, q = li & 63;
        float4 v4 = *(const float4*)(qbase + (size_t)d * LL + l0 + q);
        *(float4*)(Qs + d * 64 + q) = v4;
    }

    float mx[4], lx[4], o[4][4];
#pragma unroll
    for (int i = 0; i < 4; i++) {
        mx[i] = -1e30f; lx[i] = 0.f;
#pragma unroll
        for (int j = 0; j < 4; j++) o[i][j] = 0.f;
    }
    const float scale = 0.125f;  // 1/sqrt(64)

    for (int k0 = 0; k0 < LL; k0 += 64) {
        // Load K (natural [d][k]) and V (transposed to [k][d]).
#pragma unroll
        for (int r = 0; r < 4; r++) {
            int li = tid * 4 + r * 1024;
            int d = li >> 6, k = li & 63;
            float4 kv = *(const float4*)(kbase + (size_t)d * LL + k0 + k);
            *(float4*)(Ks + d * 64 + k) = kv;
            float4 vv = *(const float4*)(vbase + (size_t)d * LL + k0 + k);
            Vs[(k + 0) * 68 + d] = vv.x;
            Vs[(k + 1) * 68 + d] = vv.y;
            Vs[(k + 2) * 68 + d] = vv.z;
            Vs[(k + 3) * 68 + d] = vv.w;
        }
        if (tid < 64) Ms[tid] = maskb[k0 + tid];
        __syncthreads();

        // S = Q^T K  (q x k tile, 4x4 per thread)
        float s[4][4];
#pragma unroll
        for (int i = 0; i < 4; i++)
#pragma unroll
            for (int j = 0; j < 4; j++) s[i][j] = 0.f;

#pragma unroll 8
        for (int d = 0; d < 64; d++) {
            float4 a = *(const float4*)(Qs + d * 64 + qoff);
            float4 kv = *(const float4*)(Ks + d * 64 + doff);
            float av[4] = {a.x, a.y, a.z, a.w};
            float kvv[4] = {kv.x, kv.y, kv.z, kv.w};
#pragma unroll
            for (int i = 0; i < 4; i++)
#pragma unroll
                for (int j = 0; j < 4; j++) s[i][j] += av[i] * kvv[j];
        }

        // scale + key padding mask
        float msk[4];
#pragma unroll
        for (int j = 0; j < 4; j++) msk[j] = Ms[doff + j];
#pragma unroll
        for (int i = 0; i < 4; i++)
#pragma unroll
            for (int j = 0; j < 4; j++)
                s[i][j] = (msk[j] <= 0.5f) ? -1e9f : s[i][j] * scale;

        // Online softmax per q row (reduction over 16 lanes of this half-warp).
#pragma unroll
        for (int i = 0; i < 4; i++) {
            float bm = fmaxf(fmaxf(s[i][0], s[i][1]), fmaxf(s[i][2], s[i][3]));
#pragma unroll
            for (int m = 8; m; m >>= 1)
                bm = fmaxf(bm, __shfl_xor_sync(0xffffffffu, bm, m));
            float mnew = fmaxf(mx[i], bm);
            float corr = __expf(mx[i] - mnew);
            float4 p4;
            p4.x = __expf(s[i][0] - mnew);
            p4.y = __expf(s[i][1] - mnew);
            p4.z = __expf(s[i][2] - mnew);
            p4.w = __expf(s[i][3] - mnew);
            *(float4*)(Ps + (qoff + i) * 68 + doff) = p4;
            float ps = p4.x + p4.y + p4.z + p4.w;
#pragma unroll
            for (int m = 8; m; m >>= 1)
                ps += __shfl_xor_sync(0xffffffffu, ps, m);
            lx[i] = lx[i] * corr + ps;
            mx[i] = mnew;
#pragma unroll
            for (int j = 0; j < 4; j++) o[i][j] *= corr;
        }
        __syncthreads();

        // O += P * V   (q x d tile, inner over k)
#pragma unroll 8
        for (int kk = 0; kk < 64; kk++) {
            float4 vv = *(const float4*)(Vs + kk * 68 + doff);
            float p0 = Ps[(qoff + 0) * 68 + kk];
            float p1 = Ps[(qoff + 1) * 68 + kk];
            float p2 = Ps[(qoff + 2) * 68 + kk];
            float p3 = Ps[(qoff + 3) * 68 + kk];
            o[0][0] += p0 * vv.x; o[0][1] += p0 * vv.y; o[0][2] += p0 * vv.z; o[0][3] += p0 * vv.w;
            o[1][0] += p1 * vv.x; o[1][1] += p1 * vv.y; o[1][2] += p1 * vv.z; o[1][3] += p1 * vv.w;
            o[2][0] += p2 * vv.x; o[2][1] += p2 * vv.y; o[2][2] += p2 * vv.z; o[2][3] += p2 * vv.w;
            o[3][0] += p3 * vv.x; o[3][1] += p3 * vv.y; o[3][2] += p3 * vv.z; o[3][3] += p3 * vv.w;
        }
        __syncthreads();
    }

    // Normalize and write context in (B, L, C) layout (coalesced over d).
    float* cb = g_ctx + ((size_t)b * LL + l0) * CC + h * DH;
#pragma unroll
    for (int i = 0; i < 4; i++) {
        float inv = 1.f / lx[i];
        float4 r = make_float4(o[i][0] * inv, o[i][1] * inv,
                               o[i][2] * inv, o[i][3] * inv);
        *(float4*)(cb + (size_t)(qoff + i) * CC + doff) = r;
    }
}

// ---------------------------------------------------------------------------
extern "C" void kernel_launch(void* const* d_in, const int* in_sizes, int n_in,
                              void* d_out, int out_size)
{
    const float* q    = (const float*)d_in[0];
    const float* k    = (const float*)d_in[1];
    const float* v    = (const float*)d_in[2];
    const float* mask = (const float*)d_in[3];
    const float* Wq   = (const float*)d_in[4];
    const float* bq   = (const float*)d_in[5];
    const float* Wk   = (const float*)d_in[6];
    const float* bk   = (const float*)d_in[7];
    const float* Wv   = (const float*)d_in[8];
    const float* bv   = (const float*)d_in[9];
    const float* Wout = (const float*)d_in[10];
    const float* bout = (const float*)d_in[11];
    float* out = (float*)d_out;

    float *qh, *kh, *vh, *ctx;
    cudaGetSymbolAddress((void**)&qh,  g_qh);
    cudaGetSymbolAddress((void**)&kh,  g_kh);
    cudaGetSymbolAddress((void**)&vh,  g_vh);
    cudaGetSymbolAddress((void**)&ctx, g_ctx);

    dim3 grid(LL / 64, CC / 64, BB);
    dim3 blk(256);

    proj_kernel<<<grid, blk>>>(Wq, bq, q, qh);
    proj_kernel<<<grid, blk>>>(Wk, bk, k, kh);
    proj_kernel<<<grid, blk>>>(Wv, bv, v, vh);

    cudaFuncSetAttribute(attn_kernel,
                         cudaFuncAttributeMaxDynamicSharedMemorySize,
                         ATTN_SMEM_BYTES);
    dim3 agrid(LL / 64, HH, BB);
    attn_kernel<<<agrid, blk, ATTN_SMEM_BYTES>>>(mask);

    projT_kernel<<<grid, blk>>>(Wout, bout, ctx, out);
}

// round 4
// speedup vs baseline: 2.9528x; 2.9528x over previous
#include <cuda_runtime.h>
#include <cuda_bf16.h>
#include <cstdint>
#include <cstddef>

#define BB 4
#define CC 512
#define LL 2048
#define HH 8
#define DH 64
#define BL (BB*LL)

// ---------------------------------------------------------------------------
// Scratch (bf16 hi/lo pairs)
// ---------------------------------------------------------------------------
__device__ __nv_bfloat16 g_xq_hi[BL*CC], g_xq_lo[BL*CC];
__device__ __nv_bfloat16 g_xk_hi[BL*CC], g_xk_lo[BL*CC];
__device__ __nv_bfloat16 g_xv_hi[BL*CC], g_xv_lo[BL*CC];
__device__ __nv_bfloat16 g_wq_hi[CC*CC], g_wq_lo[CC*CC];
__device__ __nv_bfloat16 g_wk_hi[CC*CC], g_wk_lo[CC*CC];
__device__ __nv_bfloat16 g_wv_hi[CC*CC], g_wv_lo[CC*CC];
__device__ __nv_bfloat16 g_wo_hi[CC*CC], g_wo_lo[CC*CC];
__device__ __nv_bfloat16 g_qh_hi[BL*CC], g_qh_lo[BL*CC];   // (B,L,C)
__device__ __nv_bfloat16 g_kh_hi[BL*CC], g_kh_lo[BL*CC];   // (B,L,C)
__device__ __nv_bfloat16 g_vh_hi[BL*CC], g_vh_lo[BL*CC];   // (B,C,L)
__device__ __nv_bfloat16 g_ct_hi[BL*CC], g_ct_lo[BL*CC];   // (B,L,C)

// ---------------------------------------------------------------------------
// Helpers
// ---------------------------------------------------------------------------
__device__ __forceinline__ uint32_t smem_u32(const void* p) {
    uint32_t a;
    asm("{ .reg .u64 t; cvta.to.shared.u64 t, %1; cvt.u32.u64 %0, t; }" : "=r"(a) : "l"(p));
    return a;
}

#define LDSM4(R, a) \
    asm volatile("ldmatrix.sync.aligned.m8n8.x4.shared.b16 {%0,%1,%2,%3}, [%4];" \
        : "=r"((R)[0]), "=r"((R)[1]), "=r"((R)[2]), "=r"((R)[3]) : "r"(a))

#define CPA16(d, s) \
    asm volatile("cp.async.cg.shared.global [%0], [%1], 16;" :: "r"(d), "l"(s))
#define CPC()   asm volatile("cp.async.commit_group;" ::: "memory")
#define CPW1()  asm volatile("cp.async.wait_group 1;" ::: "memory")
#define CPWALL() asm volatile("cp.async.wait_group 0;" ::: "memory")

__device__ __forceinline__ void mma_bf16(float* c, const uint32_t* a, const uint32_t* b) {
    asm volatile("mma.sync.aligned.m16n8k16.row.col.f32.bf16.bf16.f32 "
        "{%0,%1,%2,%3}, {%4,%5,%6,%7}, {%8,%9}, {%0,%1,%2,%3};"
        : "+f"(c[0]), "+f"(c[1]), "+f"(c[2]), "+f"(c[3])
        : "r"(a[0]), "r"(a[1]), "r"(a[2]), "r"(a[3]), "r"(b[0]), "r"(b[1]));
}

__device__ __forceinline__ void split2(float x, __nv_bfloat16& h, __nv_bfloat16& l) {
    h = __float2bfloat16_rn(x);
    l = __float2bfloat16_rn(x - __bfloat162float(h));
}
__device__ __forceinline__ uint32_t pack2(__nv_bfloat16 a, __nv_bfloat16 b) {
    __nv_bfloat162 t; t.x = a; t.y = b;
    return *reinterpret_cast<uint32_t*>(&t);
}
__device__ __forceinline__ uint32_t packhi(float a, float b) {
    return pack2(__float2bfloat16_rn(a), __float2bfloat16_rn(b));
}
__device__ __forceinline__ uint32_t packlo(float a, float b) {
    __nv_bfloat16 ha = __float2bfloat16_rn(a), hb = __float2bfloat16_rn(b);
    return pack2(__float2bfloat16_rn(a - __bfloat162float(ha)),
                 __float2bfloat16_rn(b - __bfloat162float(hb)));
}

// ---------------------------------------------------------------------------
// Pre-pass: transpose (B,C,L) fp32 -> (B*L, C) bf16 hi/lo
// ---------------------------------------------------------------------------
__global__ __launch_bounds__(256) void tconv_kernel(
    const float* __restrict__ X, __nv_bfloat16* __restrict__ Thi, __nv_bfloat16* __restrict__ Tlo)
{
    __shared__ float t[32][33];
    const int b = blockIdx.z, l0 = blockIdx.x * 32, c0 = blockIdx.y * 32;
    const int tx = threadIdx.x, ty = threadIdx.y;
    const float* Xb = X + ((size_t)b * CC + c0) * LL + l0;
#pragma unroll
    for (int i = 0; i < 4; i++)
        t[ty + i * 8][tx] = Xb[(size_t)(ty + i * 8) * LL + tx];
    __syncthreads();
    const size_t ob = ((size_t)b * LL + l0) * CC + c0;
#pragma unroll
    for (int i = 0; i < 4; i++) {
        int lr = ty + i * 8;
        float v = t[tx][lr];
        __nv_bfloat16 h, l; split2(v, h, l);
        Thi[ob + (size_t)lr * CC + tx] = h;
        Tlo[ob + (size_t)lr * CC + tx] = l;
    }
}

__global__ __launch_bounds__(256) void wconv_kernel(
    const float* __restrict__ W, __nv_bfloat16* __restrict__ Whi, __nv_bfloat16* __restrict__ Wlo)
{
    int i = blockIdx.x * 256 + threadIdx.x;
    if (i < CC * CC) {
        __nv_bfloat16 h, l; split2(W[i], h, l);
        Whi[i] = h; Wlo[i] = l;
    }
}

// ---------------------------------------------------------------------------
// GEMM: D[m,n] = sum_k A[m,k]*B[n,k] (+bias), bf16 split-3 via mma.sync.
// CTA 128x128, K-chunk 64, 8 warps (4 M x 2 N), warp tile 32x64.
// MODE 0: out (B,L,C) bf16 hi/lo, bias by n
// MODE 1: out (B,C,L) bf16 hi/lo, bias by m (m = channel)
// MODE 2: out (B,C,L) fp32, bias by m
// ---------------------------------------------------------------------------
#define GM_AH 0
#define GM_AL 16384
#define GM_BH 32768
#define GM_BL 49152
#define GM_STAGE 65536
#define GM_SMEM 131072

template<int MODE>
__global__ __launch_bounds__(256, 1) void gemm_mma(
    const __nv_bfloat16* __restrict__ Ahi, const __nv_bfloat16* __restrict__ Alo,
    const __nv_bfloat16* __restrict__ Bhi, const __nv_bfloat16* __restrict__ Blo,
    const float* __restrict__ bias,
    __nv_bfloat16* __restrict__ Ohi, __nv_bfloat16* __restrict__ Olo,
    float* __restrict__ Of)
{
    extern __shared__ __align__(128) char sm[];
    const uint32_t sb = smem_u32(sm);
    const int tid = threadIdx.x, lane = tid & 31, wid = tid >> 5;
    const int warpM = wid >> 1, warpN = wid & 1;
    const int m0 = blockIdx.x * 128, n0 = blockIdx.y * 128;

    auto load_stage = [&](int s, int cch) {
        const int c0 = cch * 64;
        const uint32_t base = sb + s * GM_STAGE;
#pragma unroll
        for (int p = 0; p < 4; p++) {
            int u = p * 256 + tid;
            int row = u >> 3, quad = u & 7;
            uint32_t so = (uint32_t)(row * 128 + ((quad ^ (row & 7)) << 4));
            size_t ga = (size_t)(m0 + row) * CC + c0 + quad * 8;
            size_t gb = (size_t)(n0 + row) * CC + c0 + quad * 8;
            CPA16(base + GM_AH + so, Ahi + ga);
            CPA16(base + GM_AL + so, Alo + ga);
            CPA16(base + GM_BH + so, Bhi + gb);
            CPA16(base + GM_BL + so, Blo + gb);
        }
    };

    load_stage(0, 0); CPC();
    load_stage(1, 1); CPC();
    CPW1();
    __syncthreads();

    float C[2][8][4];
#pragma unroll
    for (int mf = 0; mf < 2; mf++)
#pragma unroll
        for (int nf = 0; nf < 8; nf++)
#pragma unroll
            for (int r = 0; r < 4; r++) C[mf][nf][r] = 0.f;

    // precomputed address pieces
    const int arow = warpM * 32 + (lane & 15);
    const int aqb  = lane >> 4;
    const int brow = warpN * 64 + (lane & 7) + ((lane & 16) >> 1);
    const int bqb  = (lane >> 3) & 1;

    for (int cch = 0; cch < 8; cch++) {
        const int s = cch & 1;
        const uint32_t Ab = sb + s * GM_STAGE + GM_AH;
        const uint32_t Alb = sb + s * GM_STAGE + GM_AL;
        const uint32_t Bb = sb + s * GM_STAGE + GM_BH;
        const uint32_t Blb = sb + s * GM_STAGE + GM_BL;
#pragma unroll
        for (int ks = 0; ks < 4; ks++) {
            uint32_t ah[2][4], al[2][4];
#pragma unroll
            for (int mf = 0; mf < 2; mf++) {
                int row = arow + mf * 16;
                int quad = 2 * ks + aqb;
                uint32_t off = (uint32_t)(row * 128 + ((quad ^ (row & 7)) << 4));
                LDSM4(ah[mf], Ab + off);
                LDSM4(al[mf], Alb + off);
            }
            uint32_t bh[8][2], bl[8][2];
#pragma unroll
            for (int g = 0; g < 4; g++) {
                int row = brow + g * 16;
                int quad = 2 * ks + bqb;
                uint32_t off = (uint32_t)(row * 128 + ((quad ^ (row & 7)) << 4));
                uint32_t t0[4], t1[4];
                LDSM4(t0, Bb + off);
                LDSM4(t1, Blb + off);
                bh[2*g][0] = t0[0]; bh[2*g][1] = t0[1];
                bh[2*g+1][0] = t0[2]; bh[2*g+1][1] = t0[3];
                bl[2*g][0] = t1[0]; bl[2*g][1] = t1[1];
                bl[2*g+1][0] = t1[2]; bl[2*g+1][1] = t1[3];
            }
#pragma unroll
            for (int mf = 0; mf < 2; mf++)
#pragma unroll
                for (int nf = 0; nf < 8; nf++) {
                    mma_bf16(C[mf][nf], ah[mf], bh[nf]);
                    mma_bf16(C[mf][nf], ah[mf], bl[nf]);
                    mma_bf16(C[mf][nf], al[mf], bh[nf]);
                }
        }
        __syncthreads();
        if (cch + 2 < 8) load_stage(s, cch + 2);
        CPC();
        CPW1();
        __syncthreads();
    }
    CPWALL();

    // epilogue
    const int mbase = m0 + warpM * 32 + (lane >> 2);
    const int nbase = n0 + warpN * 64 + 2 * (lane & 3);
#pragma unroll
    for (int mf = 0; mf < 2; mf++) {
#pragma unroll
        for (int nf = 0; nf < 8; nf++) {
            int mrow = mbase + mf * 16;
            int n = nbase + nf * 8;
            if (MODE == 0) {
                float b0 = __ldg(bias + n), b1 = __ldg(bias + n + 1);
                float f00 = C[mf][nf][0] + b0, f01 = C[mf][nf][1] + b1;
                float f10 = C[mf][nf][2] + b0, f11 = C[mf][nf][3] + b1;
                *(uint32_t*)(Ohi + (size_t)mrow * CC + n) = packhi(f00, f01);
                *(uint32_t*)(Olo + (size_t)mrow * CC + n) = packlo(f00, f01);
                *(uint32_t*)(Ohi + (size_t)(mrow + 8) * CC + n) = packhi(f10, f11);
                *(uint32_t*)(Olo + (size_t)(mrow + 8) * CC + n) = packlo(f10, f11);
            } else {
                float bva = __ldg(bias + mrow), bvb = __ldg(bias + mrow + 8);
                int bb = n >> 11, lpos = n & 2047;
                size_t ob0 = ((size_t)(bb * CC + mrow)) * LL + lpos;
                size_t ob1 = ((size_t)(bb * CC + mrow + 8)) * LL + lpos;
                float f00 = C[mf][nf][0] + bva, f01 = C[mf][nf][1] + bva;
                float f10 = C[mf][nf][2] + bvb, f11 = C[mf][nf][3] + bvb;
                if (MODE == 1) {
                    *(uint32_t*)(Ohi + ob0) = packhi(f00, f01);
                    *(uint32_t*)(Olo + ob0) = packlo(f00, f01);
                    *(uint32_t*)(Ohi + ob1) = packhi(f10, f11);
                    *(uint32_t*)(Olo + ob1) = packlo(f10, f11);
                } else {
                    *(float2*)(Of + ob0) = make_float2(f00, f01);
                    *(float2*)(Of + ob1) = make_float2(f10, f11);
                }
            }
        }
    }
}

// ---------------------------------------------------------------------------
// Flash attention via mma.sync. CTA = 128 q rows x (head, batch), 256 threads,
// warp grid 4(M) x 2(N over kpos). KV blocks of 128, cp.async double-buffered.
// Softmax without max subtraction (scores bounded); P packed to bf16 hi/lo in
// registers directly in A-fragment layout. Cross-warp O + lsum reduce at end.
// ---------------------------------------------------------------------------
#define AT_QH 0
#define AT_QL 16384
#define AT_ST(s) (32768 + (s)*65536)
#define AT_KH 0
#define AT_KL 16384
#define AT_VH 32768
#define AT_VL 49152
#define AT_MASK(s) (163840 + (s)*512)
#define AT_LSUM 164864
#define AT_RED 32768
#define AT_SMEM 165888

__global__ __launch_bounds__(256, 1) void attn_mma(
    const float* __restrict__ mask,
    const __nv_bfloat16* __restrict__ Qhi, const __nv_bfloat16* __restrict__ Qlo,
    const __nv_bfloat16* __restrict__ Khi, const __nv_bfloat16* __restrict__ Klo,
    const __nv_bfloat16* __restrict__ Vhi, const __nv_bfloat16* __restrict__ Vlo,
    __nv_bfloat16* __restrict__ Chi, __nv_bfloat16* __restrict__ Clo)
{
    extern __shared__ __align__(128) char sm[];
    const uint32_t sb = smem_u32(sm);
    const int tid = threadIdx.x, lane = tid & 31, wid = tid >> 5;
    const int warpM = wid >> 1, warpN = wid & 1;
    const int q0 = blockIdx.x * 128, h = blockIdx.y, b = blockIdx.z;
    const float scale = 0.125f;  // 1/sqrt(64)

    // load Q tile (plain stores)
#pragma unroll
    for (int p = 0; p < 4; p++) {
        int u = p * 256 + tid;
        int row = u >> 3, quad = u & 7;
        uint32_t so = (uint32_t)(row * 128 + ((quad ^ (row & 7)) << 4));
        size_t g = ((size_t)(b * LL + q0 + row)) * CC + h * DH + quad * 8;
        *(uint4*)(sm + AT_QH + so) = *(const uint4*)(Qhi + g);
        *(uint4*)(sm + AT_QL + so) = *(const uint4*)(Qlo + g);
    }

    auto load_stage = [&](int s, int kb) {
        const int k0 = kb * 128;
        const uint32_t base = sb + AT_ST(s);
#pragma unroll
        for (int p = 0; p < 4; p++) {
            int u = p * 256 + tid;
            int row = u >> 3, quad = u & 7;
            uint32_t so = (uint32_t)(row * 128 + ((quad ^ (row & 7)) << 4));
            size_t gk = ((size_t)(b * LL + k0 + row)) * CC + h * DH + quad * 8;
            CPA16(base + AT_KH + so, Khi + gk);
            CPA16(base + AT_KL + so, Klo + gk);
        }
#pragma unroll
        for (int p = 0; p < 4; p++) {
            int u = p * 256 + tid;
            int row = u >> 4, quad = u & 15;
            uint32_t so = (uint32_t)(row * 256 + ((quad ^ (row & 7)) << 4));
            size_t gv = ((size_t)(b * CC + h * DH + row)) * LL + k0 + quad * 8;
            CPA16(base + AT_VH + so, Vhi + gv);
            CPA16(base + AT_VL + so, Vlo + gv);
        }
        if (tid < 128)
            ((float*)(sm + AT_MASK(s)))[tid] = mask[(size_t)b * LL + k0 + tid];
    };

    load_stage(0, 0); CPC();
    load_stage(1, 1); CPC();
    CPW1();
    __syncthreads();

    float O[2][8][4];
#pragma unroll
    for (int mf = 0; mf < 2; mf++)
#pragma unroll
        for (int nf = 0; nf < 8; nf++)
#pragma unroll
            for (int r = 0; r < 4; r++) O[mf][nf][r] = 0.f;
    float ls[2][2] = {{0.f, 0.f}, {0.f, 0.f}};

    const int arow = warpM * 32 + (lane & 15);
    const int aqb  = lane >> 4;
    const int brow = warpN * 64 + (lane & 7) + ((lane & 16) >> 1);   // K tile rows
    const int vrow = (lane & 7) + ((lane & 16) >> 1);                // V tile rows (d)
    const int bqb  = (lane >> 3) & 1;

    for (int kb = 0; kb < 16; kb++) {
        const int s = kb & 1;
        const uint32_t Kb = sb + AT_ST(s) + AT_KH;
        const uint32_t Klb = sb + AT_ST(s) + AT_KL;
        const uint32_t Vb = sb + AT_ST(s) + AT_VH;
        const uint32_t Vlb = sb + AT_ST(s) + AT_VL;
        const float* msk = (const float*)(sm + AT_MASK(s));

        // ---- S = Q K^T ----
        float S[2][8][4];
#pragma unroll
        for (int mf = 0; mf < 2; mf++)
#pragma unroll
            for (int nf = 0; nf < 8; nf++)
#pragma unroll
                for (int r = 0; r < 4; r++) S[mf][nf][r] = 0.f;

#pragma unroll
        for (int ks = 0; ks < 4; ks++) {
            uint32_t qh[2][4], ql[2][4];
#pragma unroll
            for (int mf = 0; mf < 2; mf++) {
                int row = arow + mf * 16;
                int quad = 2 * ks + aqb;
                uint32_t off = (uint32_t)(row * 128 + ((quad ^ (row & 7)) << 4));
                LDSM4(qh[mf], sb + AT_QH + off);
                LDSM4(ql[mf], sb + AT_QL + off);
            }
            uint32_t kh[8][2], kl[8][2];
#pragma unroll
            for (int g = 0; g < 4; g++) {
                int row = brow + g * 16;
                int quad = 2 * ks + bqb;
                uint32_t off = (uint32_t)(row * 128 + ((quad ^ (row & 7)) << 4));
                uint32_t t0[4], t1[4];
                LDSM4(t0, Kb + off);
                LDSM4(t1, Klb + off);
                kh[2*g][0] = t0[0]; kh[2*g][1] = t0[1];
                kh[2*g+1][0] = t0[2]; kh[2*g+1][1] = t0[3];
                kl[2*g][0] = t1[0]; kl[2*g][1] = t1[1];
                kl[2*g+1][0] = t1[2]; kl[2*g+1][1] = t1[3];
            }
#pragma unroll
            for (int mf = 0; mf < 2; mf++)
#pragma unroll
                for (int nf = 0; nf < 8; nf++) {
                    mma_bf16(S[mf][nf], qh[mf], kh[nf]);
                    mma_bf16(S[mf][nf], qh[mf], kl[nf]);
                    mma_bf16(S[mf][nf], ql[mf], kh[nf]);
                }
        }

        // ---- softmax: exp + mask, pack P hi/lo into A-fragment regs ----
        uint32_t ph[2][4][4], pl[2][4][4];
#pragma unroll
        for (int nf = 0; nf < 8; nf++) {
            int ki = warpN * 64 + nf * 8 + 2 * (lane & 3);
            float mv0 = msk[ki], mv1 = msk[ki + 1];
            int ks2 = nf >> 1, half = nf & 1;
#pragma unroll
            for (int mf = 0; mf < 2; mf++) {
                float e00 = (mv0 > 0.5f) ? __expf(S[mf][nf][0] * scale) : 0.f;
                float e01 = (mv1 > 0.5f) ? __expf(S[mf][nf][1] * scale) : 0.f;
                float e10 = (mv0 > 0.5f) ? __expf(S[mf][nf][2] * scale) : 0.f;
                float e11 = (mv1 > 0.5f) ? __expf(S[mf][nf][3] * scale) : 0.f;
                ls[mf][0] += e00 + e01;
                ls[mf][1] += e10 + e11;
                ph[mf][ks2][2 * half + 0] = packhi(e00, e01);
                ph[mf][ks2][2 * half + 1] = packhi(e10, e11);
                pl[mf][ks2][2 * half + 0] = packlo(e00, e01);
                pl[mf][ks2][2 * half + 1] = packlo(e10, e11);
            }
        }

        // ---- O += P V^T ----
#pragma unroll
        for (int ks = 0; ks < 4; ks++) {
            uint32_t vh[8][2], vl[8][2];
#pragma unroll
            for (int g = 0; g < 4; g++) {
                int row = vrow + g * 16;
                int quad = warpN * 8 + 2 * ks + bqb;
                uint32_t off = (uint32_t)(row * 256 + ((quad ^ (row & 7)) << 4));
                uint32_t t0[4], t1[4];
                LDSM4(t0, Vb + off);
                LDSM4(t1, Vlb + off);
                vh[2*g][0] = t0[0]; vh[2*g][1] = t0[1];
                vh[2*g+1][0] = t0[2]; vh[2*g+1][1] = t0[3];
                vl[2*g][0] = t1[0]; vl[2*g][1] = t1[1];
                vl[2*g+1][0] = t1[2]; vl[2*g+1][1] = t1[3];
            }
#pragma unroll
            for (int mf = 0; mf < 2; mf++)
#pragma unroll
                for (int nf = 0; nf < 8; nf++) {
                    mma_bf16(O[mf][nf], ph[mf][ks], vh[nf]);
                    mma_bf16(O[mf][nf], ph[mf][ks], vl[nf]);
                    mma_bf16(O[mf][nf], pl[mf][ks], vh[nf]);
                }
        }

        __syncthreads();
        if (kb + 2 < 16) load_stage(s, kb + 2);
        CPC();
        CPW1();
        __syncthreads();
    }
    CPWALL();

    // ---- lsum reduction (over lane%4 and the 2 N-warps) ----
    float* lsum_sm = (float*)(sm + AT_LSUM);
#pragma unroll
    for (int mf = 0; mf < 2; mf++)
#pragma unroll
        for (int r = 0; r < 2; r++) {
            float v = ls[mf][r];
            v += __shfl_xor_sync(0xffffffffu, v, 1);
            v += __shfl_xor_sync(0xffffffffu, v, 2);
            if ((lane & 3) == 0)
                lsum_sm[(warpM * 32 + mf * 16 + (lane >> 2) + r * 8) * 2 + warpN] = v;
        }
    __syncthreads();

    // ---- O cross-warp reduce (warpN 1 -> smem, warpN 0 adds + writes) ----
    float* red = (float*)(sm + AT_RED + warpM * 9216);
    if (warpN == 1) {
#pragma unroll
        for (int mf = 0; mf < 2; mf++)
#pragma unroll
            for (int nf = 0; nf < 8; nf++) {
                int lr = mf * 16 + (lane >> 2);
                int n = nf * 8 + 2 * (lane & 3);
                red[lr * 72 + n] = O[mf][nf][0];
                red[lr * 72 + n + 1] = O[mf][nf][1];
                red[(lr + 8) * 72 + n] = O[mf][nf][2];
                red[(lr + 8) * 72 + n + 1] = O[mf][nf][3];
            }
    }
    __syncthreads();
    if (warpN == 0) {
#pragma unroll
        for (int mf = 0; mf < 2; mf++) {
            int lr0 = mf * 16 + (lane >> 2);
            int lr1 = lr0 + 8;
            float t0 = lsum_sm[(warpM * 32 + lr0) * 2] + lsum_sm[(warpM * 32 + lr0) * 2 + 1];
            float t1 = lsum_sm[(warpM * 32 + lr1) * 2] + lsum_sm[(warpM * 32 + lr1) * 2 + 1];
            float inv0 = (t0 > 0.f) ? 1.f / t0 : 0.f;
            float inv1 = (t1 > 0.f) ? 1.f / t1 : 0.f;
#pragma unroll
            for (int nf = 0; nf < 8; nf++) {
                int n = nf * 8 + 2 * (lane & 3);
                float f00 = (O[mf][nf][0] + red[lr0 * 72 + n]) * inv0;
                float f01 = (O[mf][nf][1] + red[lr0 * 72 + n + 1]) * inv0;
                float f10 = (O[mf][nf][2] + red[lr1 * 72 + n]) * inv1;
                float f11 = (O[mf][nf][3] + red[lr1 * 72 + n + 1]) * inv1;
                size_t g0 = ((size_t)(b * LL + q0 + warpM * 32 + lr0)) * CC + h * DH + n;
                size_t g1 = ((size_t)(b * LL + q0 + warpM * 32 + lr1)) * CC + h * DH + n;
                *(uint32_t*)(Chi + g0) = packhi(f00, f01);
                *(uint32_t*)(Clo + g0) = packlo(f00, f01);
                *(uint32_t*)(Chi + g1) = packhi(f10, f11);
                *(uint32_t*)(Clo + g1) = packlo(f10, f11);
            }
        }
    }
}

// ---------------------------------------------------------------------------
extern "C" void kernel_launch(void* const* d_in, const int* in_sizes, int n_in,
                              void* d_out, int out_size)
{
    const float* q    = (const float*)d_in[0];
    const float* k    = (const float*)d_in[1];
    const float* v    = (const float*)d_in[2];
    const float* mask = (const float*)d_in[3];
    const float* Wq   = (const float*)d_in[4];
    const float* bq   = (const float*)d_in[5];
    const float* Wk   = (const float*)d_in[6];
    const float* bk   = (const float*)d_in[7];
    const float* Wv   = (const float*)d_in[8];
    const float* bv   = (const float*)d_in[9];
    const float* Wout = (const float*)d_in[10];
    const float* bout = (const float*)d_in[11];
    float* out = (float*)d_out;

    __nv_bfloat16 *xqh, *xql, *xkh, *xkl, *xvh, *xvl;
    __nv_bfloat16 *wqh, *wql, *wkh, *wkl, *wvh, *wvl, *woh, *wol;
    __nv_bfloat16 *qhh, *qhl, *khh, *khl, *vhh, *vhl, *cth, *ctl;
    cudaGetSymbolAddress((void**)&xqh, g_xq_hi); cudaGetSymbolAddress((void**)&xql, g_xq_lo);
    cudaGetSymbolAddress((void**)&xkh, g_xk_hi); cudaGetSymbolAddress((void**)&xkl, g_xk_lo);
    cudaGetSymbolAddress((void**)&xvh, g_xv_hi); cudaGetSymbolAddress((void**)&xvl, g_xv_lo);
    cudaGetSymbolAddress((void**)&wqh, g_wq_hi); cudaGetSymbolAddress((void**)&wql, g_wq_lo);
    cudaGetSymbolAddress((void**)&wkh, g_wk_hi); cudaGetSymbolAddress((void**)&wkl, g_wk_lo);
    cudaGetSymbolAddress((void**)&wvh, g_wv_hi); cudaGetSymbolAddress((void**)&wvl, g_wv_lo);
    cudaGetSymbolAddress((void**)&woh, g_wo_hi); cudaGetSymbolAddress((void**)&wol, g_wo_lo);
    cudaGetSymbolAddress((void**)&qhh, g_qh_hi); cudaGetSymbolAddress((void**)&qhl, g_qh_lo);
    cudaGetSymbolAddress((void**)&khh, g_kh_hi); cudaGetSymbolAddress((void**)&khl, g_kh_lo);
    cudaGetSymbolAddress((void**)&vhh, g_vh_hi); cudaGetSymbolAddress((void**)&vhl, g_vh_lo);
    cudaGetSymbolAddress((void**)&cth, g_ct_hi); cudaGetSymbolAddress((void**)&ctl, g_ct_lo);

    cudaFuncSetAttribute(gemm_mma<0>, cudaFuncAttributeMaxDynamicSharedMemorySize, GM_SMEM);
    cudaFuncSetAttribute(gemm_mma<1>, cudaFuncAttributeMaxDynamicSharedMemorySize, GM_SMEM);
    cudaFuncSetAttribute(gemm_mma<2>, cudaFuncAttributeMaxDynamicSharedMemorySize, GM_SMEM);
    cudaFuncSetAttribute(attn_mma, cudaFuncAttributeMaxDynamicSharedMemorySize, AT_SMEM);

    dim3 tgrid(LL / 32, CC / 32, BB), tblk(32, 8);
    tconv_kernel<<<tgrid, tblk>>>(q, xqh, xql);
    tconv_kernel<<<tgrid, tblk>>>(k, xkh, xkl);
    tconv_kernel<<<tgrid, tblk>>>(v, xvh, xvl);

    int wgrid = (CC * CC + 255) / 256;
    wconv_kernel<<<wgrid, 256>>>(Wq, wqh, wql);
    wconv_kernel<<<wgrid, 256>>>(Wk, wkh, wkl);
    wconv_kernel<<<wgrid, 256>>>(Wv, wvh, wvl);
    wconv_kernel<<<wgrid, 256>>>(Wout, woh, wol);

    // Q, K projections -> (B,L,C)
    dim3 gA(BL / 128, CC / 128);
    gemm_mma<0><<<gA, 256, GM_SMEM>>>(xqh, xql, wqh, wql, bq, qhh, qhl, nullptr);
    gemm_mma<0><<<gA, 256, GM_SMEM>>>(xkh, xkl, wkh, wkl, bk, khh, khl, nullptr);
    // V projection (W as A) -> (B,C,L)
    dim3 gB(CC / 128, BL / 128);
    gemm_mma<1><<<gB, 256, GM_SMEM>>>(wvh, wvl, xvh, xvl, bv, vhh, vhl, nullptr);

    dim3 agrid(LL / 128, HH, BB);
    attn_mma<<<agrid, 256, AT_SMEM>>>(mask, qhh, qhl, khh, khl, vhh, vhl, cth, ctl);

    // Output projection (W as A) -> (B,C,L) fp32
    gemm_mma<2><<<gB, 256, GM_SMEM>>>(woh, wol, cth, ctl, bout, nullptr, nullptr, out);
}

// round 5
// speedup vs baseline: 3.9355x; 1.3328x over previous
#include <cuda_runtime.h>
#include <cuda_bf16.h>
#include <cuda_fp16.h>
#include <cstdint>
#include <cstddef>

#define BB 4
#define CC 512
#define LL 2048
#define HH 8
#define DH 64
#define BL (BB*LL)

// ---------------------------------------------------------------------------
// Scratch
// ---------------------------------------------------------------------------
__device__ __nv_bfloat16 g_xq_hi[BL*CC], g_xq_lo[BL*CC];
__device__ __nv_bfloat16 g_xk_hi[BL*CC], g_xk_lo[BL*CC];
__device__ __nv_bfloat16 g_xv_hi[BL*CC], g_xv_lo[BL*CC];
__device__ __nv_bfloat16 g_wq_hi[CC*CC], g_wq_lo[CC*CC];
__device__ __nv_bfloat16 g_wk_hi[CC*CC], g_wk_lo[CC*CC];
__device__ __nv_bfloat16 g_wv_hi[CC*CC], g_wv_lo[CC*CC];
__device__ __nv_bfloat16 g_wo_hi[CC*CC], g_wo_lo[CC*CC];
__device__ __half g_qhH[BL*CC];                            // (B,L,C) fp16
__device__ __half g_khH[BL*CC];                            // (B,L,C) fp16
__device__ __half g_vhH[BL*CC];                            // (B,C,L) fp16
__device__ __nv_bfloat16 g_ct_hi[BL*CC], g_ct_lo[BL*CC];   // (B,L,C) bf16 hi/lo

// ---------------------------------------------------------------------------
// Helpers
// ---------------------------------------------------------------------------
__device__ __forceinline__ uint32_t smem_u32(const void* p) {
    uint32_t a;
    asm("{ .reg .u64 t; cvta.to.shared.u64 t, %1; cvt.u32.u64 %0, t; }" : "=r"(a) : "l"(p));
    return a;
}

#define LDSM4(R, a) \
    asm volatile("ldmatrix.sync.aligned.m8n8.x4.shared.b16 {%0,%1,%2,%3}, [%4];" \
        : "=r"((R)[0]), "=r"((R)[1]), "=r"((R)[2]), "=r"((R)[3]) : "r"(a))

#define CPA16(d, s) \
    asm volatile("cp.async.cg.shared.global [%0], [%1], 16;" :: "r"(d), "l"(s))
#define CPC()   asm volatile("cp.async.commit_group;" ::: "memory")
#define CPW1()  asm volatile("cp.async.wait_group 1;" ::: "memory")
#define CPW2()  asm volatile("cp.async.wait_group 2;" ::: "memory")
#define CPWALL() asm volatile("cp.async.wait_group 0;" ::: "memory")

__device__ __forceinline__ void mma_bf16(float* c, const uint32_t* a, const uint32_t* b) {
    asm volatile("mma.sync.aligned.m16n8k16.row.col.f32.bf16.bf16.f32 "
        "{%0,%1,%2,%3}, {%4,%5,%6,%7}, {%8,%9}, {%0,%1,%2,%3};"
        : "+f"(c[0]), "+f"(c[1]), "+f"(c[2]), "+f"(c[3])
        : "r"(a[0]), "r"(a[1]), "r"(a[2]), "r"(a[3]), "r"(b[0]), "r"(b[1]));
}
__device__ __forceinline__ void mma_f16(float* c, const uint32_t* a, const uint32_t* b) {
    asm volatile("mma.sync.aligned.m16n8k16.row.col.f32.f16.f16.f32 "
        "{%0,%1,%2,%3}, {%4,%5,%6,%7}, {%8,%9}, {%0,%1,%2,%3};"
        : "+f"(c[0]), "+f"(c[1]), "+f"(c[2]), "+f"(c[3])
        : "r"(a[0]), "r"(a[1]), "r"(a[2]), "r"(a[3]), "r"(b[0]), "r"(b[1]));
}

__device__ __forceinline__ void split2(float x, __nv_bfloat16& h, __nv_bfloat16& l) {
    h = __float2bfloat16_rn(x);
    l = __float2bfloat16_rn(x - __bfloat162float(h));
}
__device__ __forceinline__ uint32_t pack2(__nv_bfloat16 a, __nv_bfloat16 b) {
    __nv_bfloat162 t; t.x = a; t.y = b;
    return *reinterpret_cast<uint32_t*>(&t);
}
__device__ __forceinline__ uint32_t packhi(float a, float b) {
    return pack2(__float2bfloat16_rn(a), __float2bfloat16_rn(b));
}
__device__ __forceinline__ uint32_t packlo(float a, float b) {
    __nv_bfloat16 ha = __float2bfloat16_rn(a), hb = __float2bfloat16_rn(b);
    return pack2(__float2bfloat16_rn(a - __bfloat162float(ha)),
                 __float2bfloat16_rn(b - __bfloat162float(hb)));
}
__device__ __forceinline__ uint32_t packh2(float a, float b) {
    __half2 t = __floats2half2_rn(a, b);
    return *reinterpret_cast<uint32_t*>(&t);
}
__device__ __forceinline__ uint32_t packh2lo(float a, float b) {
    __half ha = __float2half_rn(a), hb = __float2half_rn(b);
    __half2 t = __halves2half2(__float2half_rn(a - __half2float(ha)),
                               __float2half_rn(b - __half2float(hb)));
    return *reinterpret_cast<uint32_t*>(&t);
}

// ---------------------------------------------------------------------------
// Pre-pass: transpose (B,C,L) fp32 -> (B*L, C) bf16 hi/lo
// ---------------------------------------------------------------------------
__global__ __launch_bounds__(256) void tconv_kernel(
    const float* __restrict__ X, __nv_bfloat16* __restrict__ Thi, __nv_bfloat16* __restrict__ Tlo)
{
    __shared__ float t[32][33];
    const int b = blockIdx.z, l0 = blockIdx.x * 32, c0 = blockIdx.y * 32;
    const int tx = threadIdx.x, ty = threadIdx.y;
    const float* Xb = X + ((size_t)b * CC + c0) * LL + l0;
#pragma unroll
    for (int i = 0; i < 4; i++)
        t[ty + i * 8][tx] = Xb[(size_t)(ty + i * 8) * LL + tx];
    __syncthreads();
    const size_t ob = ((size_t)b * LL + l0) * CC + c0;
#pragma unroll
    for (int i = 0; i < 4; i++) {
        int lr = ty + i * 8;
        float v = t[tx][lr];
        __nv_bfloat16 h, l; split2(v, h, l);
        Thi[ob + (size_t)lr * CC + tx] = h;
        Tlo[ob + (size_t)lr * CC + tx] = l;
    }
}

__global__ __launch_bounds__(256) void wconv_kernel(
    const float* __restrict__ W, __nv_bfloat16* __restrict__ Whi, __nv_bfloat16* __restrict__ Wlo)
{
    int i = blockIdx.x * 256 + threadIdx.x;
    if (i < CC * CC) {
        __nv_bfloat16 h, l; split2(W[i], h, l);
        Whi[i] = h; Wlo[i] = l;
    }
}

// ---------------------------------------------------------------------------
// GEMM: D[m,n] = sum_k A[m,k]*B[n,k] (+bias), bf16 split-3 via mma.sync.
// CTA 128x128, K-chunk 64, 8 warps (4 M x 2 N), warp tile 32x64.
// MODE 0: out fp16 single, (B,L,C), bias by n      [Q, K heads]
// MODE 1: out fp16 single, (B,C,L), bias by m      [V heads]
// MODE 2: out fp32, (B,C,L), bias by m             [final output]
// ---------------------------------------------------------------------------
#define GM_AH 0
#define GM_AL 16384
#define GM_BH 32768
#define GM_BL 49152
#define GM_STAGE 65536
#define GM_SMEM 131072

template<int MODE>
__global__ __launch_bounds__(256, 1) void gemm_mma(
    const __nv_bfloat16* __restrict__ Ahi, const __nv_bfloat16* __restrict__ Alo,
    const __nv_bfloat16* __restrict__ Bhi, const __nv_bfloat16* __restrict__ Blo,
    const float* __restrict__ bias,
    __half* __restrict__ Oh, float* __restrict__ Of)
{
    extern __shared__ __align__(128) char sm[];
    const uint32_t sb = smem_u32(sm);
    const int tid = threadIdx.x, lane = tid & 31, wid = tid >> 5;
    const int warpM = wid >> 1, warpN = wid & 1;
    const int m0 = blockIdx.x * 128, n0 = blockIdx.y * 128;

    auto load_stage = [&](int s, int cch) {
        const int c0 = cch * 64;
        const uint32_t base = sb + s * GM_STAGE;
#pragma unroll
        for (int p = 0; p < 4; p++) {
            int u = p * 256 + tid;
            int row = u >> 3, quad = u & 7;
            uint32_t so = (uint32_t)(row * 128 + ((quad ^ (row & 7)) << 4));
            size_t ga = (size_t)(m0 + row) * CC + c0 + quad * 8;
            size_t gb = (size_t)(n0 + row) * CC + c0 + quad * 8;
            CPA16(base + GM_AH + so, Ahi + ga);
            CPA16(base + GM_AL + so, Alo + ga);
            CPA16(base + GM_BH + so, Bhi + gb);
            CPA16(base + GM_BL + so, Blo + gb);
        }
    };

    load_stage(0, 0); CPC();
    load_stage(1, 1); CPC();
    CPW1();
    __syncthreads();

    float C[2][8][4];
#pragma unroll
    for (int mf = 0; mf < 2; mf++)
#pragma unroll
        for (int nf = 0; nf < 8; nf++)
#pragma unroll
            for (int r = 0; r < 4; r++) C[mf][nf][r] = 0.f;

    const int arow = warpM * 32 + (lane & 15);
    const int aqb  = lane >> 4;
    const int brow = warpN * 64 + (lane & 7) + ((lane & 16) >> 1);
    const int bqb  = (lane >> 3) & 1;

    for (int cch = 0; cch < 8; cch++) {
        const int s = cch & 1;
        const uint32_t Ab = sb + s * GM_STAGE + GM_AH;
        const uint32_t Alb = sb + s * GM_STAGE + GM_AL;
        const uint32_t Bb = sb + s * GM_STAGE + GM_BH;
        const uint32_t Blb = sb + s * GM_STAGE + GM_BL;
#pragma unroll
        for (int ks = 0; ks < 4; ks++) {
            uint32_t ah[2][4], al[2][4];
#pragma unroll
            for (int mf = 0; mf < 2; mf++) {
                int row = arow + mf * 16;
                int quad = 2 * ks + aqb;
                uint32_t off = (uint32_t)(row * 128 + ((quad ^ (row & 7)) << 4));
                LDSM4(ah[mf], Ab + off);
                LDSM4(al[mf], Alb + off);
            }
            uint32_t bh[8][2], bl[8][2];
#pragma unroll
            for (int g = 0; g < 4; g++) {
                int row = brow + g * 16;
                int quad = 2 * ks + bqb;
                uint32_t off = (uint32_t)(row * 128 + ((quad ^ (row & 7)) << 4));
                uint32_t t0[4], t1[4];
                LDSM4(t0, Bb + off);
                LDSM4(t1, Blb + off);
                bh[2*g][0] = t0[0]; bh[2*g][1] = t0[1];
                bh[2*g+1][0] = t0[2]; bh[2*g+1][1] = t0[3];
                bl[2*g][0] = t1[0]; bl[2*g][1] = t1[1];
                bl[2*g+1][0] = t1[2]; bl[2*g+1][1] = t1[3];
            }
#pragma unroll
            for (int mf = 0; mf < 2; mf++)
#pragma unroll
                for (int nf = 0; nf < 8; nf++) {
                    mma_bf16(C[mf][nf], ah[mf], bh[nf]);
                    mma_bf16(C[mf][nf], ah[mf], bl[nf]);
                    mma_bf16(C[mf][nf], al[mf], bh[nf]);
                }
        }
        __syncthreads();
        if (cch + 2 < 8) load_stage(s, cch + 2);
        CPC();
        CPW1();
        __syncthreads();
    }
    CPWALL();

    // epilogue
    const int mbase = m0 + warpM * 32 + (lane >> 2);
    const int nbase = n0 + warpN * 64 + 2 * (lane & 3);
#pragma unroll
    for (int mf = 0; mf < 2; mf++) {
#pragma unroll
        for (int nf = 0; nf < 8; nf++) {
            int mrow = mbase + mf * 16;
            int n = nbase + nf * 8;
            if (MODE == 0) {
                float b0 = __ldg(bias + n), b1 = __ldg(bias + n + 1);
                *(uint32_t*)(Oh + (size_t)mrow * CC + n) =
                    packh2(C[mf][nf][0] + b0, C[mf][nf][1] + b1);
                *(uint32_t*)(Oh + (size_t)(mrow + 8) * CC + n) =
                    packh2(C[mf][nf][2] + b0, C[mf][nf][3] + b1);
            } else {
                float bva = __ldg(bias + mrow), bvb = __ldg(bias + mrow + 8);
                int bb = n >> 11, lpos = n & 2047;
                size_t ob0 = ((size_t)(bb * CC + mrow)) * LL + lpos;
                size_t ob1 = ((size_t)(bb * CC + mrow + 8)) * LL + lpos;
                if (MODE == 1) {
                    *(uint32_t*)(Oh + ob0) = packh2(C[mf][nf][0] + bva, C[mf][nf][1] + bva);
                    *(uint32_t*)(Oh + ob1) = packh2(C[mf][nf][2] + bvb, C[mf][nf][3] + bvb);
                } else {
                    *(float2*)(Of + ob0) = make_float2(C[mf][nf][0] + bva, C[mf][nf][1] + bva);
                    *(float2*)(Of + ob1) = make_float2(C[mf][nf][2] + bvb, C[mf][nf][3] + bvb);
                }
            }
        }
    }
}

// ---------------------------------------------------------------------------
// Flash attention, fp16 mma.sync. CTA = 128 q rows x (head, batch), 256 thr,
// warps 4(M) x 2(N over kpos). KV blocks of 128, 3-stage cp.async.
// S = Q K^T in ONE fp16 pass (error ~7e-5 after scale). P split fp16 hi/lo;
// O += Phi V + Plo V (V single fp16, error ~3e-4). No max subtraction.
// ---------------------------------------------------------------------------
#define AT_Q 0
#define AT_STRIDE 33280
#define AT_ST(s) (16384 + (s)*AT_STRIDE)
#define AT_K 0
#define AT_V 16384
#define AT_MSK 32768
#define AT_LSUM (16384 + 3*AT_STRIDE)
#define AT_RED 16384
#define AT_SMEM (AT_LSUM + 1024)

__global__ __launch_bounds__(256, 1) void attn_mma(
    const float* __restrict__ mask,
    const __half* __restrict__ Qg, const __half* __restrict__ Kg,
    const __half* __restrict__ Vg,
    __nv_bfloat16* __restrict__ Chi, __nv_bfloat16* __restrict__ Clo)
{
    extern __shared__ __align__(128) char sm[];
    const uint32_t sb = smem_u32(sm);
    const int tid = threadIdx.x, lane = tid & 31, wid = tid >> 5;
    const int warpM = wid >> 1, warpN = wid & 1;
    const int q0 = blockIdx.x * 128, h = blockIdx.y, b = blockIdx.z;
    const float scale = 0.125f;  // 1/sqrt(64)

    // load Q tile (plain stores), 128 rows x 64 half, swizzled 128B rows
#pragma unroll
    for (int p = 0; p < 4; p++) {
        int u = p * 256 + tid;
        int row = u >> 3, quad = u & 7;
        uint32_t so = (uint32_t)(row * 128 + ((quad ^ (row & 7)) << 4));
        size_t g = ((size_t)(b * LL + q0 + row)) * CC + h * DH + quad * 8;
        *(uint4*)(sm + AT_Q + so) = *(const uint4*)(Qg + g);
    }

    auto load_stage = [&](int s, int kb) {
        const int k0 = kb * 128;
        const uint32_t base = sb + AT_ST(s);
#pragma unroll
        for (int p = 0; p < 4; p++) {
            int u = p * 256 + tid;
            int row = u >> 3, quad = u & 7;
            uint32_t so = (uint32_t)(row * 128 + ((quad ^ (row & 7)) << 4));
            size_t gk = ((size_t)(b * LL + k0 + row)) * CC + h * DH + quad * 8;
            CPA16(base + AT_K + so, Kg + gk);
        }
#pragma unroll
        for (int p = 0; p < 4; p++) {
            int u = p * 256 + tid;
            int row = u >> 4, quad = u & 15;
            uint32_t so = (uint32_t)(row * 256 + ((quad ^ (row & 7)) << 4));
            size_t gv = ((size_t)(b * CC + h * DH + row)) * LL + k0 + quad * 8;
            CPA16(base + AT_V + so, Vg + gv);
        }
        if (tid < 128)
            ((float*)(sm + base - sb + AT_MSK))[tid] = mask[(size_t)b * LL + k0 + tid];
    };

    load_stage(0, 0); CPC();
    load_stage(1, 1); CPC();
    load_stage(2, 2); CPC();
    CPW2();
    __syncthreads();

    float O[2][8][4];
#pragma unroll
    for (int mf = 0; mf < 2; mf++)
#pragma unroll
        for (int nf = 0; nf < 8; nf++)
#pragma unroll
            for (int r = 0; r < 4; r++) O[mf][nf][r] = 0.f;
    float ls[2][2] = {{0.f, 0.f}, {0.f, 0.f}};

    const int arow = warpM * 32 + (lane & 15);
    const int aqb  = lane >> 4;
    const int brow = warpN * 64 + (lane & 7) + ((lane & 16) >> 1);   // K rows
    const int vrow = (lane & 7) + ((lane & 16) >> 1);                // V rows (d)
    const int bqb  = (lane >> 3) & 1;

    for (int kb = 0; kb < 16; kb++) {
        const int s = kb % 3;
        const uint32_t Kb = sb + AT_ST(s) + AT_K;
        const uint32_t Vb = sb + AT_ST(s) + AT_V;
        const float* msk = (const float*)(sm + AT_ST(s) + AT_MSK);

        // ---- S = Q K^T (1 fp16 pass) ----
        float S[2][8][4];
#pragma unroll
        for (int mf = 0; mf < 2; mf++)
#pragma unroll
            for (int nf = 0; nf < 8; nf++)
#pragma unroll
                for (int r = 0; r < 4; r++) S[mf][nf][r] = 0.f;

#pragma unroll
        for (int ks = 0; ks < 4; ks++) {
            uint32_t qf[2][4];
#pragma unroll
            for (int mf = 0; mf < 2; mf++) {
                int row = arow + mf * 16;
                int quad = 2 * ks + aqb;
                uint32_t off = (uint32_t)(row * 128 + ((quad ^ (row & 7)) << 4));
                LDSM4(qf[mf], sb + AT_Q + off);
            }
            uint32_t kf[8][2];
#pragma unroll
            for (int g = 0; g < 4; g++) {
                int row = brow + g * 16;
                int quad = 2 * ks + bqb;
                uint32_t off = (uint32_t)(row * 128 + ((quad ^ (row & 7)) << 4));
                uint32_t t0[4];
                LDSM4(t0, Kb + off);
                kf[2*g][0] = t0[0]; kf[2*g][1] = t0[1];
                kf[2*g+1][0] = t0[2]; kf[2*g+1][1] = t0[3];
            }
#pragma unroll
            for (int mf = 0; mf < 2; mf++)
#pragma unroll
                for (int nf = 0; nf < 8; nf++)
                    mma_f16(S[mf][nf], qf[mf], kf[nf]);
        }

        // ---- softmax: mask + exp; pack P fp16 hi/lo into A-fragment regs ----
        uint32_t ph[2][4][4], pl[2][4][4];
#pragma unroll
        for (int nf = 0; nf < 8; nf++) {
            int ki = warpN * 64 + nf * 8 + 2 * (lane & 3);
            float mv0 = msk[ki], mv1 = msk[ki + 1];
            int ks2 = nf >> 1, half = nf & 1;
#pragma unroll
            for (int mf = 0; mf < 2; mf++) {
                float e00 = (mv0 > 0.5f) ? __expf(S[mf][nf][0] * scale) : 0.f;
                float e01 = (mv1 > 0.5f) ? __expf(S[mf][nf][1] * scale) : 0.f;
                float e10 = (mv0 > 0.5f) ? __expf(S[mf][nf][2] * scale) : 0.f;
                float e11 = (mv1 > 0.5f) ? __expf(S[mf][nf][3] * scale) : 0.f;
                ls[mf][0] += e00 + e01;
                ls[mf][1] += e10 + e11;
                ph[mf][ks2][2 * half + 0] = packh2(e00, e01);
                ph[mf][ks2][2 * half + 1] = packh2(e10, e11);
                pl[mf][ks2][2 * half + 0] = packh2lo(e00, e01);
                pl[mf][ks2][2 * half + 1] = packh2lo(e10, e11);
            }
        }

        // ---- O += P V^T (2 fp16 passes: Phi, Plo) ----
#pragma unroll
        for (int ks = 0; ks < 4; ks++) {
            uint32_t vf[8][2];
#pragma unroll
            for (int g = 0; g < 4; g++) {
                int row = vrow + g * 16;
                int quad = warpN * 8 + 2 * ks + bqb;
                uint32_t off = (uint32_t)(row * 256 + ((quad ^ (row & 7)) << 4));
                uint32_t t0[4];
                LDSM4(t0, Vb + off);
                vf[2*g][0] = t0[0]; vf[2*g][1] = t0[1];
                vf[2*g+1][0] = t0[2]; vf[2*g+1][1] = t0[3];
            }
#pragma unroll
            for (int mf = 0; mf < 2; mf++)
#pragma unroll
                for (int nf = 0; nf < 8; nf++) {
                    mma_f16(O[mf][nf], ph[mf][ks], vf[nf]);
                    mma_f16(O[mf][nf], pl[mf][ks], vf[nf]);
                }
        }

        __syncthreads();
        if (kb + 3 < 16) load_stage(s, kb + 3);
        CPC();
        CPW2();
        __syncthreads();
    }
    CPWALL();

    // ---- lsum reduction (over lane%4 and the 2 N-warps) ----
    float* lsum_sm = (float*)(sm + AT_LSUM);
#pragma unroll
    for (int mf = 0; mf < 2; mf++)
#pragma unroll
        for (int r = 0; r < 2; r++) {
            float v = ls[mf][r];
            v += __shfl_xor_sync(0xffffffffu, v, 1);
            v += __shfl_xor_sync(0xffffffffu, v, 2);
            if ((lane & 3) == 0)
                lsum_sm[(warpM * 32 + mf * 16 + (lane >> 2) + r * 8) * 2 + warpN] = v;
        }
    __syncthreads();

    // ---- O cross-warp reduce (warpN 1 -> smem, warpN 0 adds + writes) ----
    float* red = (float*)(sm + AT_RED + warpM * 9216);
    if (warpN == 1) {
#pragma unroll
        for (int mf = 0; mf < 2; mf++)
#pragma unroll
            for (int nf = 0; nf < 8; nf++) {
                int lr = mf * 16 + (lane >> 2);
                int n = nf * 8 + 2 * (lane & 3);
                red[lr * 72 + n] = O[mf][nf][0];
                red[lr * 72 + n + 1] = O[mf][nf][1];
                red[(lr + 8) * 72 + n] = O[mf][nf][2];
                red[(lr + 8) * 72 + n + 1] = O[mf][nf][3];
            }
    }
    __syncthreads();
    if (warpN == 0) {
#pragma unroll
        for (int mf = 0; mf < 2; mf++) {
            int lr0 = mf * 16 + (lane >> 2);
            int lr1 = lr0 + 8;
            float t0 = lsum_sm[(warpM * 32 + lr0) * 2] + lsum_sm[(warpM * 32 + lr0) * 2 + 1];
            float t1 = lsum_sm[(warpM * 32 + lr1) * 2] + lsum_sm[(warpM * 32 + lr1) * 2 + 1];
            float inv0 = (t0 > 0.f) ? 1.f / t0 : 0.f;
            float inv1 = (t1 > 0.f) ? 1.f / t1 : 0.f;
#pragma unroll
            for (int nf = 0; nf < 8; nf++) {
                int n = nf * 8 + 2 * (lane & 3);
                float f00 = (O[mf][nf][0] + red[lr0 * 72 + n]) * inv0;
                float f01 = (O[mf][nf][1] + red[lr0 * 72 + n + 1]) * inv0;
                float f10 = (O[mf][nf][2] + red[lr1 * 72 + n]) * inv1;
                float f11 = (O[mf][nf][3] + red[lr1 * 72 + n + 1]) * inv1;
                size_t g0 = ((size_t)(b * LL + q0 + warpM * 32 + lr0)) * CC + h * DH + n;
                size_t g1 = ((size_t)(b * LL + q0 + warpM * 32 + lr1)) * CC + h * DH + n;
                *(uint32_t*)(Chi + g0) = packhi(f00, f01);
                *(uint32_t*)(Clo + g0) = packlo(f00, f01);
                *(uint32_t*)(Chi + g1) = packhi(f10, f11);
                *(uint32_t*)(Clo + g1) = packlo(f10, f11);
            }
        }
    }
}

// ---------------------------------------------------------------------------
extern "C" void kernel_launch(void* const* d_in, const int* in_sizes, int n_in,
                              void* d_out, int out_size)
{
    const float* q    = (const float*)d_in[0];
    const float* k    = (const float*)d_in[1];
    const float* v    = (const float*)d_in[2];
    const float* mask = (const float*)d_in[3];
    const float* Wq   = (const float*)d_in[4];
    const float* bq   = (const float*)d_in[5];
    const float* Wk   = (const float*)d_in[6];
    const float* bk   = (const float*)d_in[7];
    const float* Wv   = (const float*)d_in[8];
    const float* bv   = (const float*)d_in[9];
    const float* Wout = (const float*)d_in[10];
    const float* bout = (const float*)d_in[11];
    float* out = (float*)d_out;

    __nv_bfloat16 *xqh, *xql, *xkh, *xkl, *xvh, *xvl;
    __nv_bfloat16 *wqh, *wql, *wkh, *wkl, *wvh, *wvl, *woh, *wol;
    __nv_bfloat16 *cth, *ctl;
    __half *qhH, *khH, *vhH;
    cudaGetSymbolAddress((void**)&xqh, g_xq_hi); cudaGetSymbolAddress((void**)&xql, g_xq_lo);
    cudaGetSymbolAddress((void**)&xkh, g_xk_hi); cudaGetSymbolAddress((void**)&xkl, g_xk_lo);
    cudaGetSymbolAddress((void**)&xvh, g_xv_hi); cudaGetSymbolAddress((void**)&xvl, g_xv_lo);
    cudaGetSymbolAddress((void**)&wqh, g_wq_hi); cudaGetSymbolAddress((void**)&wql, g_wq_lo);
    cudaGetSymbolAddress((void**)&wkh, g_wk_hi); cudaGetSymbolAddress((void**)&wkl, g_wk_lo);
    cudaGetSymbolAddress((void**)&wvh, g_wv_hi); cudaGetSymbolAddress((void**)&wvl, g_wv_lo);
    cudaGetSymbolAddress((void**)&woh, g_wo_hi); cudaGetSymbolAddress((void**)&wol, g_wo_lo);
    cudaGetSymbolAddress((void**)&qhH, g_qhH);
    cudaGetSymbolAddress((void**)&khH, g_khH);
    cudaGetSymbolAddress((void**)&vhH, g_vhH);
    cudaGetSymbolAddress((void**)&cth, g_ct_hi); cudaGetSymbolAddress((void**)&ctl, g_ct_lo);

    cudaFuncSetAttribute(gemm_mma<0>, cudaFuncAttributeMaxDynamicSharedMemorySize, GM_SMEM);
    cudaFuncSetAttribute(gemm_mma<1>, cudaFuncAttributeMaxDynamicSharedMemorySize, GM_SMEM);
    cudaFuncSetAttribute(gemm_mma<2>, cudaFuncAttributeMaxDynamicSharedMemorySize, GM_SMEM);
    cudaFuncSetAttribute(attn_mma, cudaFuncAttributeMaxDynamicSharedMemorySize, AT_SMEM);

    dim3 tgrid(LL / 32, CC / 32, BB), tblk(32, 8);
    tconv_kernel<<<tgrid, tblk>>>(q, xqh, xql);
    tconv_kernel<<<tgrid, tblk>>>(k, xkh, xkl);
    tconv_kernel<<<tgrid, tblk>>>(v, xvh, xvl);

    int wgrid = (CC * CC + 255) / 256;
    wconv_kernel<<<wgrid, 256>>>(Wq, wqh, wql);
    wconv_kernel<<<wgrid, 256>>>(Wk, wkh, wkl);
    wconv_kernel<<<wgrid, 256>>>(Wv, wvh, wvl);
    wconv_kernel<<<wgrid, 256>>>(Wout, woh, wol);

    // Q, K projections -> (B,L,C) fp16
    dim3 gA(BL / 128, CC / 128);
    gemm_mma<0><<<gA, 256, GM_SMEM>>>(xqh, xql, wqh, wql, bq, qhH, nullptr);
    gemm_mma<0><<<gA, 256, GM_SMEM>>>(xkh, xkl, wkh, wkl, bk, khH, nullptr);
    // V projection (W as A) -> (B,C,L) fp16
    dim3 gB(CC / 128, BL / 128);
    gemm_mma<1><<<gB, 256, GM_SMEM>>>(wvh, wvl, xvh, xvl, bv, vhH, nullptr);

    dim3 agrid(LL / 128, HH, BB);
    attn_mma<<<agrid, 256, AT_SMEM>>>(mask, qhH, khH, vhH, cth, ctl);

    // Output projection (W as A) -> (B,C,L) fp32
    gemm_mma<2><<<gB, 256, GM_SMEM>>>(woh, wol, cth, ctl, bout, nullptr, out);
}

// round 6
// speedup vs baseline: 4.0525x; 1.0297x over previous
#include <cuda_runtime.h>
#include <cuda_bf16.h>
#include <cuda_fp16.h>
#include <cstdint>
#include <cstddef>

#define BB 4
#define CC 512
#define LL 2048
#define HH 8
#define DH 64
#define BL (BB*LL)

// ---------------------------------------------------------------------------
// Scratch (all single fp16)
// ---------------------------------------------------------------------------
__device__ __half g_xq[BL*CC];     // (B,L,C) transposed inputs
__device__ __half g_xk[BL*CC];
__device__ __half g_xv[BL*CC];
__device__ __half g_wq[CC*CC];
__device__ __half g_wk[CC*CC];
__device__ __half g_wv[CC*CC];
__device__ __half g_wo[CC*CC];
__device__ __half g_qhH[BL*CC];    // (B,L,C)
__device__ __half g_khH[BL*CC];    // (B,L,C)
__device__ __half g_vhH[BL*CC];    // (B,C,L)
__device__ __half g_ct[BL*CC];     // (B,L,C)

// ---------------------------------------------------------------------------
// Helpers
// ---------------------------------------------------------------------------
__device__ __forceinline__ uint32_t smem_u32(const void* p) {
    uint32_t a;
    asm("{ .reg .u64 t; cvta.to.shared.u64 t, %1; cvt.u32.u64 %0, t; }" : "=r"(a) : "l"(p));
    return a;
}

#define LDSM4(R, a) \
    asm volatile("ldmatrix.sync.aligned.m8n8.x4.shared.b16 {%0,%1,%2,%3}, [%4];" \
        : "=r"((R)[0]), "=r"((R)[1]), "=r"((R)[2]), "=r"((R)[3]) : "r"(a))

#define CPA16(d, s) \
    asm volatile("cp.async.cg.shared.global [%0], [%1], 16;" :: "r"(d), "l"(s))
#define CPC()   asm volatile("cp.async.commit_group;" ::: "memory")
#define CPW2()  asm volatile("cp.async.wait_group 2;" ::: "memory")
#define CPWALL() asm volatile("cp.async.wait_group 0;" ::: "memory")

__device__ __forceinline__ void mma_f16(float* c, const uint32_t* a, const uint32_t* b) {
    asm volatile("mma.sync.aligned.m16n8k16.row.col.f32.f16.f16.f32 "
        "{%0,%1,%2,%3}, {%4,%5,%6,%7}, {%8,%9}, {%0,%1,%2,%3};"
        : "+f"(c[0]), "+f"(c[1]), "+f"(c[2]), "+f"(c[3])
        : "r"(a[0]), "r"(a[1]), "r"(a[2]), "r"(a[3]), "r"(b[0]), "r"(b[1]));
}

__device__ __forceinline__ uint32_t packh2(float a, float b) {
    __half2 t = __floats2half2_rn(a, b);
    return *reinterpret_cast<uint32_t*>(&t);
}

// ---------------------------------------------------------------------------
// Pre-pass: transpose (B,C,L) fp32 -> (B*L, C) fp16, all 3 tensors in one grid
// ---------------------------------------------------------------------------
__global__ __launch_bounds__(256) void tconv_kernel(
    const float* __restrict__ Xq, const float* __restrict__ Xk, const float* __restrict__ Xv,
    __half* __restrict__ Tq, __half* __restrict__ Tk, __half* __restrict__ Tv)
{
    __shared__ float t[32][33];
    const int zz = blockIdx.z;
    const int which = zz >> 2, b = zz & 3;
    const float* X = (which == 0) ? Xq : (which == 1) ? Xk : Xv;
    __half* T = (which == 0) ? Tq : (which == 1) ? Tk : Tv;
    const int l0 = blockIdx.x * 32, c0 = blockIdx.y * 32;
    const int tx = threadIdx.x, ty = threadIdx.y;
    const float* Xb = X + ((size_t)b * CC + c0) * LL + l0;
#pragma unroll
    for (int i = 0; i < 4; i++)
        t[ty + i * 8][tx] = Xb[(size_t)(ty + i * 8) * LL + tx];
    __syncthreads();
    const size_t ob = ((size_t)b * LL + l0) * CC + c0;
#pragma unroll
    for (int i = 0; i < 4; i++) {
        int lr = ty + i * 8;
        T[ob + (size_t)lr * CC + tx] = __float2half_rn(t[tx][lr]);
    }
}

// All 4 weight matrices in one launch: i in [0, 4*CC*CC)
__global__ __launch_bounds__(256) void wconv_kernel(
    const float* __restrict__ W0, const float* __restrict__ W1,
    const float* __restrict__ W2, const float* __restrict__ W3,
    __half* __restrict__ O0, __half* __restrict__ O1,
    __half* __restrict__ O2, __half* __restrict__ O3)
{
    int gi = blockIdx.x * 256 + threadIdx.x;
    int which = gi >> 18;           // CC*CC = 262144 = 2^18
    int i = gi & 0x3FFFF;
    const float* W = (which == 0) ? W0 : (which == 1) ? W1 : (which == 2) ? W2 : W3;
    __half* O = (which == 0) ? O0 : (which == 1) ? O1 : (which == 2) ? O2 : O3;
    O[i] = __float2half_rn(W[i]);
}

// ---------------------------------------------------------------------------
// GEMM: D[m,n] = sum_k A[m,k]*B[n,k] (+bias), single-pass fp16 mma.sync.
// CTA 128x128, K-chunk 64, 3-stage cp.async, 8 warps (4 M x 2 N).
// MODE 0: out fp16, (B,L,C), bias by n      [Q, K heads]
// MODE 1: out fp16, (B,C,L), bias by m      [V heads]
// MODE 2: out fp32, (B,C,L), bias by m      [final output]
// ---------------------------------------------------------------------------
#define GM_A 0
#define GM_B 16384
#define GM_STAGE 32768
#define GM_SMEM (3*GM_STAGE)

template<int MODE>
__global__ __launch_bounds__(256, 1) void gemm_mma(
    const __half* __restrict__ A, const __half* __restrict__ B,
    const float* __restrict__ bias,
    __half* __restrict__ Oh, float* __restrict__ Of)
{
    extern __shared__ __align__(128) char sm[];
    const uint32_t sb = smem_u32(sm);
    const int tid = threadIdx.x, lane = tid & 31, wid = tid >> 5;
    const int warpM = wid >> 1, warpN = wid & 1;
    const int m0 = blockIdx.x * 128, n0 = blockIdx.y * 128;

    auto load_stage = [&](int s, int cch) {
        const int c0 = cch * 64;
        const uint32_t base = sb + s * GM_STAGE;
#pragma unroll
        for (int p = 0; p < 4; p++) {
            int u = p * 256 + tid;
            int row = u >> 3, quad = u & 7;
            uint32_t so = (uint32_t)(row * 128 + ((quad ^ (row & 7)) << 4));
            CPA16(base + GM_A + so, A + (size_t)(m0 + row) * CC + c0 + quad * 8);
            CPA16(base + GM_B + so, B + (size_t)(n0 + row) * CC + c0 + quad * 8);
        }
    };

    load_stage(0, 0); CPC();
    load_stage(1, 1); CPC();
    load_stage(2, 2); CPC();
    CPW2();
    __syncthreads();

    float C[2][8][4];
#pragma unroll
    for (int mf = 0; mf < 2; mf++)
#pragma unroll
        for (int nf = 0; nf < 8; nf++)
#pragma unroll
            for (int r = 0; r < 4; r++) C[mf][nf][r] = 0.f;

    const int arow = warpM * 32 + (lane & 15);
    const int aqb  = lane >> 4;
    const int brow = warpN * 64 + (lane & 7) + ((lane & 16) >> 1);
    const int bqb  = (lane >> 3) & 1;

    for (int cch = 0; cch < 8; cch++) {
        const int s = cch % 3;
        const uint32_t Ab = sb + s * GM_STAGE + GM_A;
        const uint32_t Bb = sb + s * GM_STAGE + GM_B;
#pragma unroll
        for (int ks = 0; ks < 4; ks++) {
            uint32_t af[2][4];
#pragma unroll
            for (int mf = 0; mf < 2; mf++) {
                int row = arow + mf * 16;
                int quad = 2 * ks + aqb;
                uint32_t off = (uint32_t)(row * 128 + ((quad ^ (row & 7)) << 4));
                LDSM4(af[mf], Ab + off);
            }
            uint32_t bf[8][2];
#pragma unroll
            for (int g = 0; g < 4; g++) {
                int row = brow + g * 16;
                int quad = 2 * ks + bqb;
                uint32_t off = (uint32_t)(row * 128 + ((quad ^ (row & 7)) << 4));
                uint32_t t0[4];
                LDSM4(t0, Bb + off);
                bf[2*g][0] = t0[0]; bf[2*g][1] = t0[1];
                bf[2*g+1][0] = t0[2]; bf[2*g+1][1] = t0[3];
            }
#pragma unroll
            for (int mf = 0; mf < 2; mf++)
#pragma unroll
                for (int nf = 0; nf < 8; nf++)
                    mma_f16(C[mf][nf], af[mf], bf[nf]);
        }
        __syncthreads();
        if (cch + 3 < 8) load_stage(s, cch + 3);
        CPC();
        CPW2();
        __syncthreads();
    }
    CPWALL();

    // epilogue
    const int mbase = m0 + warpM * 32 + (lane >> 2);
    const int nbase = n0 + warpN * 64 + 2 * (lane & 3);
#pragma unroll
    for (int mf = 0; mf < 2; mf++) {
#pragma unroll
        for (int nf = 0; nf < 8; nf++) {
            int mrow = mbase + mf * 16;
            int n = nbase + nf * 8;
            if (MODE == 0) {
                float b0 = __ldg(bias + n), b1 = __ldg(bias + n + 1);
                *(uint32_t*)(Oh + (size_t)mrow * CC + n) =
                    packh2(C[mf][nf][0] + b0, C[mf][nf][1] + b1);
                *(uint32_t*)(Oh + (size_t)(mrow + 8) * CC + n) =
                    packh2(C[mf][nf][2] + b0, C[mf][nf][3] + b1);
            } else {
                float bva = __ldg(bias + mrow), bvb = __ldg(bias + mrow + 8);
                int bb = n >> 11, lpos = n & 2047;
                size_t ob0 = ((size_t)(bb * CC + mrow)) * LL + lpos;
                size_t ob1 = ((size_t)(bb * CC + mrow + 8)) * LL + lpos;
                if (MODE == 1) {
                    *(uint32_t*)(Oh + ob0) = packh2(C[mf][nf][0] + bva, C[mf][nf][1] + bva);
                    *(uint32_t*)(Oh + ob1) = packh2(C[mf][nf][2] + bvb, C[mf][nf][3] + bvb);
                } else {
                    *(float2*)(Of + ob0) = make_float2(C[mf][nf][0] + bva, C[mf][nf][1] + bva);
                    *(float2*)(Of + ob1) = make_float2(C[mf][nf][2] + bvb, C[mf][nf][3] + bvb);
                }
            }
        }
    }
}

// ---------------------------------------------------------------------------
// Flash attention, single-pass fp16 mma.sync. CTA = 128 q x (head, batch),
// 256 threads, warps 4(M) x 2(N over kpos). KV blocks of 128, 3-stage cp.async.
// No max subtraction (scores bounded). P single fp16. Ctx out single fp16.
// ---------------------------------------------------------------------------
#define AT_Q 0
#define AT_STRIDE 33280
#define AT_ST(s) (16384 + (s)*AT_STRIDE)
#define AT_K 0
#define AT_V 16384
#define AT_MSK 32768
#define AT_LSUM (16384 + 3*AT_STRIDE)
#define AT_RED 16384
#define AT_SMEM (AT_LSUM + 1024)

__global__ __launch_bounds__(256, 1) void attn_mma(
    const float* __restrict__ mask,
    const __half* __restrict__ Qg, const __half* __restrict__ Kg,
    const __half* __restrict__ Vg,
    __half* __restrict__ Cg)
{
    extern __shared__ __align__(128) char sm[];
    const uint32_t sb = smem_u32(sm);
    const int tid = threadIdx.x, lane = tid & 31, wid = tid >> 5;
    const int warpM = wid >> 1, warpN = wid & 1;
    const int q0 = blockIdx.x * 128, h = blockIdx.y, b = blockIdx.z;
    const float scale = 0.125f;  // 1/sqrt(64)

    // load Q tile (plain stores), 128 rows x 64 half, swizzled 128B rows
#pragma unroll
    for (int p = 0; p < 4; p++) {
        int u = p * 256 + tid;
        int row = u >> 3, quad = u & 7;
        uint32_t so = (uint32_t)(row * 128 + ((quad ^ (row & 7)) << 4));
        size_t g = ((size_t)(b * LL + q0 + row)) * CC + h * DH + quad * 8;
        *(uint4*)(sm + AT_Q + so) = *(const uint4*)(Qg + g);
    }

    auto load_stage = [&](int s, int kb) {
        const int k0 = kb * 128;
        const uint32_t base = sb + AT_ST(s);
#pragma unroll
        for (int p = 0; p < 4; p++) {
            int u = p * 256 + tid;
            int row = u >> 3, quad = u & 7;
            uint32_t so = (uint32_t)(row * 128 + ((quad ^ (row & 7)) << 4));
            CPA16(base + AT_K + so, Kg + ((size_t)(b * LL + k0 + row)) * CC + h * DH + quad * 8);
        }
#pragma unroll
        for (int p = 0; p < 4; p++) {
            int u = p * 256 + tid;
            int row = u >> 4, quad = u & 15;
            uint32_t so = (uint32_t)(row * 256 + ((quad ^ (row & 7)) << 4));
            CPA16(base + AT_V + so, Vg + ((size_t)(b * CC + h * DH + row)) * LL + k0 + quad * 8);
        }
        if (tid < 128)
            ((float*)(sm + base - sb + AT_MSK))[tid] = mask[(size_t)b * LL + k0 + tid];
    };

    load_stage(0, 0); CPC();
    load_stage(1, 1); CPC();
    load_stage(2, 2); CPC();
    CPW2();
    __syncthreads();

    float O[2][8][4];
#pragma unroll
    for (int mf = 0; mf < 2; mf++)
#pragma unroll
        for (int nf = 0; nf < 8; nf++)
#pragma unroll
            for (int r = 0; r < 4; r++) O[mf][nf][r] = 0.f;
    float ls[2][2] = {{0.f, 0.f}, {0.f, 0.f}};

    const int arow = warpM * 32 + (lane & 15);
    const int aqb  = lane >> 4;
    const int brow = warpN * 64 + (lane & 7) + ((lane & 16) >> 1);   // K rows
    const int vrow = (lane & 7) + ((lane & 16) >> 1);                // V rows (d)
    const int bqb  = (lane >> 3) & 1;

    for (int kb = 0; kb < 16; kb++) {
        const int s = kb % 3;
        const uint32_t Kb = sb + AT_ST(s) + AT_K;
        const uint32_t Vb = sb + AT_ST(s) + AT_V;
        const float* msk = (const float*)(sm + AT_ST(s) + AT_MSK);

        // ---- S = Q K^T ----
        float S[2][8][4];
#pragma unroll
        for (int mf = 0; mf < 2; mf++)
#pragma unroll
            for (int nf = 0; nf < 8; nf++)
#pragma unroll
                for (int r = 0; r < 4; r++) S[mf][nf][r] = 0.f;

#pragma unroll
        for (int ks = 0; ks < 4; ks++) {
            uint32_t qf[2][4];
#pragma unroll
            for (int mf = 0; mf < 2; mf++) {
                int row = arow + mf * 16;
                int quad = 2 * ks + aqb;
                uint32_t off = (uint32_t)(row * 128 + ((quad ^ (row & 7)) << 4));
                LDSM4(qf[mf], sb + AT_Q + off);
            }
            uint32_t kf[8][2];
#pragma unroll
            for (int g = 0; g < 4; g++) {
                int row = brow + g * 16;
                int quad = 2 * ks + bqb;
                uint32_t off = (uint32_t)(row * 128 + ((quad ^ (row & 7)) << 4));
                uint32_t t0[4];
                LDSM4(t0, Kb + off);
                kf[2*g][0] = t0[0]; kf[2*g][1] = t0[1];
                kf[2*g+1][0] = t0[2]; kf[2*g+1][1] = t0[3];
            }
#pragma unroll
            for (int mf = 0; mf < 2; mf++)
#pragma unroll
                for (int nf = 0; nf < 8; nf++)
                    mma_f16(S[mf][nf], qf[mf], kf[nf]);
        }

        // ---- softmax: mask + exp; pack P fp16 into A-fragment regs ----
        uint32_t ph[2][4][4];
#pragma unroll
        for (int nf = 0; nf < 8; nf++) {
            int ki = warpN * 64 + nf * 8 + 2 * (lane & 3);
            float mv0 = msk[ki], mv1 = msk[ki + 1];
            int ks2 = nf >> 1, half = nf & 1;
#pragma unroll
            for (int mf = 0; mf < 2; mf++) {
                float e00 = (mv0 > 0.5f) ? __expf(S[mf][nf][0] * scale) : 0.f;
                float e01 = (mv1 > 0.5f) ? __expf(S[mf][nf][1] * scale) : 0.f;
                float e10 = (mv0 > 0.5f) ? __expf(S[mf][nf][2] * scale) : 0.f;
                float e11 = (mv1 > 0.5f) ? __expf(S[mf][nf][3] * scale) : 0.f;
                ls[mf][0] += e00 + e01;
                ls[mf][1] += e10 + e11;
                ph[mf][ks2][2 * half + 0] = packh2(e00, e01);
                ph[mf][ks2][2 * half + 1] = packh2(e10, e11);
            }
        }

        // ---- O += P V^T ----
#pragma unroll
        for (int ks = 0; ks < 4; ks++) {
            uint32_t vf[8][2];
#pragma unroll
            for (int g = 0; g < 4; g++) {
                int row = vrow + g * 16;
                int quad = warpN * 8 + 2 * ks + bqb;
                uint32_t off = (uint32_t)(row * 256 + ((quad ^ (row & 7)) << 4));
                uint32_t t0[4];
                LDSM4(t0, Vb + off);
                vf[2*g][0] = t0[0]; vf[2*g][1] = t0[1];
                vf[2*g+1][0] = t0[2]; vf[2*g+1][1] = t0[3];
            }
#pragma unroll
            for (int mf = 0; mf < 2; mf++)
#pragma unroll
                for (int nf = 0; nf < 8; nf++)
                    mma_f16(O[mf][nf], ph[mf][ks], vf[nf]);
        }

        __syncthreads();
        if (kb + 3 < 16) load_stage(s, kb + 3);
        CPC();
        CPW2();
        __syncthreads();
    }
    CPWALL();

    // ---- lsum reduction (over lane%4 and the 2 N-warps) ----
    float* lsum_sm = (float*)(sm + AT_LSUM);
#pragma unroll
    for (int mf = 0; mf < 2; mf++)
#pragma unroll
        for (int r = 0; r < 2; r++) {
            float v = ls[mf][r];
            v += __shfl_xor_sync(0xffffffffu, v, 1);
            v += __shfl_xor_sync(0xffffffffu, v, 2);
            if ((lane & 3) == 0)
                lsum_sm[(warpM * 32 + mf * 16 + (lane >> 2) + r * 8) * 2 + warpN] = v;
        }
    __syncthreads();

    // ---- O cross-warp reduce (warpN 1 -> smem, warpN 0 adds + writes) ----
    float* red = (float*)(sm + AT_RED + warpM * 9216);
    if (warpN == 1) {
#pragma unroll
        for (int mf = 0; mf < 2; mf++)
#pragma unroll
            for (int nf = 0; nf < 8; nf++) {
                int lr = mf * 16 + (lane >> 2);
                int n = nf * 8 + 2 * (lane & 3);
                red[lr * 72 + n] = O[mf][nf][0];
                red[lr * 72 + n + 1] = O[mf][nf][1];
                red[(lr + 8) * 72 + n] = O[mf][nf][2];
                red[(lr + 8) * 72 + n + 1] = O[mf][nf][3];
            }
    }
    __syncthreads();
    if (warpN == 0) {
#pragma unroll
        for (int mf = 0; mf < 2; mf++) {
            int lr0 = mf * 16 + (lane >> 2);
            int lr1 = lr0 + 8;
            float t0 = lsum_sm[(warpM * 32 + lr0) * 2] + lsum_sm[(warpM * 32 + lr0) * 2 + 1];
            float t1 = lsum_sm[(warpM * 32 + lr1) * 2] + lsum_sm[(warpM * 32 + lr1) * 2 + 1];
            float inv0 = (t0 > 0.f) ? 1.f / t0 : 0.f;
            float inv1 = (t1 > 0.f) ? 1.f / t1 : 0.f;
#pragma unroll
            for (int nf = 0; nf < 8; nf++) {
                int n = nf * 8 + 2 * (lane & 3);
                float f00 = (O[mf][nf][0] + red[lr0 * 72 + n]) * inv0;
                float f01 = (O[mf][nf][1] + red[lr0 * 72 + n + 1]) * inv0;
                float f10 = (O[mf][nf][2] + red[lr1 * 72 + n]) * inv1;
                float f11 = (O[mf][nf][3] + red[lr1 * 72 + n + 1]) * inv1;
                size_t g0 = ((size_t)(b * LL + q0 + warpM * 32 + lr0)) * CC + h * DH + n;
                size_t g1 = ((size_t)(b * LL + q0 + warpM * 32 + lr1)) * CC + h * DH + n;
                *(uint32_t*)(Cg + g0) = packh2(f00, f01);
                *(uint32_t*)(Cg + g1) = packh2(f10, f11);
            }
        }
    }
}

// ---------------------------------------------------------------------------
extern "C" void kernel_launch(void* const* d_in, const int* in_sizes, int n_in,
                              void* d_out, int out_size)
{
    const float* q    = (const float*)d_in[0];
    const float* k    = (const float*)d_in[1];
    const float* v    = (const float*)d_in[2];
    const float* mask = (const float*)d_in[3];
    const float* Wq   = (const float*)d_in[4];
    const float* bq   = (const float*)d_in[5];
    const float* Wk   = (const float*)d_in[6];
    const float* bk   = (const float*)d_in[7];
    const float* Wv   = (const float*)d_in[8];
    const float* bv   = (const float*)d_in[9];
    const float* Wout = (const float*)d_in[10];
    const float* bout = (const float*)d_in[11];
    float* out = (float*)d_out;

    __half *xq, *xk, *xv, *wq, *wk, *wv, *wo, *qhH, *khH, *vhH, *ct;
    cudaGetSymbolAddress((void**)&xq, g_xq);
    cudaGetSymbolAddress((void**)&xk, g_xk);
    cudaGetSymbolAddress((void**)&xv, g_xv);
    cudaGetSymbolAddress((void**)&wq, g_wq);
    cudaGetSymbolAddress((void**)&wk, g_wk);
    cudaGetSymbolAddress((void**)&wv, g_wv);
    cudaGetSymbolAddress((void**)&wo, g_wo);
    cudaGetSymbolAddress((void**)&qhH, g_qhH);
    cudaGetSymbolAddress((void**)&khH, g_khH);
    cudaGetSymbolAddress((void**)&vhH, g_vhH);
    cudaGetSymbolAddress((void**)&ct, g_ct);

    cudaFuncSetAttribute(gemm_mma<0>, cudaFuncAttributeMaxDynamicSharedMemorySize, GM_SMEM);
    cudaFuncSetAttribute(gemm_mma<1>, cudaFuncAttributeMaxDynamicSharedMemorySize, GM_SMEM);
    cudaFuncSetAttribute(gemm_mma<2>, cudaFuncAttributeMaxDynamicSharedMemorySize, GM_SMEM);
    cudaFuncSetAttribute(attn_mma, cudaFuncAttributeMaxDynamicSharedMemorySize, AT_SMEM);

    dim3 tgrid(LL / 32, CC / 32, BB * 3), tblk(32, 8);
    tconv_kernel<<<tgrid, tblk>>>(q, k, v, xq, xk, xv);

    wconv_kernel<<<4 * CC * CC / 256, 256>>>(Wq, Wk, Wv, Wout, wq, wk, wv, wo);

    // Q, K projections -> (B,L,C) fp16
    dim3 gA(BL / 128, CC / 128);
    gemm_mma<0><<<gA, 256, GM_SMEM>>>(xq, wq, bq, qhH, nullptr);
    gemm_mma<0><<<gA, 256, GM_SMEM>>>(xk, wk, bk, khH, nullptr);
    // V projection (W as A) -> (B,C,L) fp16
    dim3 gB(CC / 128, BL / 128);
    gemm_mma<1><<<gB, 256, GM_SMEM>>>(wv, xv, bv, vhH, nullptr);

    dim3 agrid(LL / 128, HH, BB);
    attn_mma<<<agrid, 256, AT_SMEM>>>(mask, qhH, khH, vhH, ct);

    // Output projection (W as A) -> (B,C,L) fp32
    gemm_mma<2><<<gB, 256, GM_SMEM>>>(wo, ct, bout, nullptr, out);
}